// round 12
// baseline (speedup 1.0000x reference)
#include <cuda_runtime.h>
#include <math.h>

// Shapes fixed by setup_inputs
#define LLL 3
#define BBB 2
#define QQQ 100
#define CCC 2
#define NGT 20
#define HM  128
#define HF  512
#define DSZ 64
#define PPX (DSZ*DSZ)        // 4096
#define LB  (LLL*BBB)        // 6
#define BN  (BBB*NGT)        // 40
#define MQ  (LLL*BBB*QQQ)    // 600
#define NPAIR (LLL*BBB*NGT)  // 120

#define NBLK_PRE 592         // 4 blocks/SM on 148 SMs
#define MDS1_UNITS (BN*HF/4) // 5120 (4 rows/unit)
#define MDS2_UNITS (BN*16)   // 640

#define CVT_STRIDE 132       // k_cost vertical-stage row stride

// ---------------- static device scratch (no allocation) ----------------
__device__ float  d_w2w[DSZ][16];
__device__ int    d_w2s[DSZ];
__device__ float  d_mw[DSZ][8];
__device__ int    d_ms[DSZ];
__device__ float  d_tmp1[BN*HF*DSZ];
__device__ float  d_mds[BN*PPX];
__device__ float  d_msp[BN*16];
__device__ unsigned d_gbits[BN*HF*16];
__device__ int    d_costTi[LB*NGT*QQQ];   // quantized cost (scale 2^20)
__device__ int    d_qmatch[LB*NGT];
__device__ float4 d_part[NPAIR*64];       // mask-loss partials

// ---- grid barrier state (count self-resets via atomicInc wrap) ----
__device__ unsigned g_count = 0;
__device__ volatile unsigned g_gen = 0;

__device__ __forceinline__ void grid_barrier() {
    __syncthreads();
    if (threadIdx.x == 0) {
        unsigned gen = g_gen;
        __threadfence();
        unsigned t = atomicInc(&g_count, NBLK_PRE - 1);
        if (t == NBLK_PRE - 1) {
            __threadfence();
            g_gen = gen + 1;
        } else {
            while (g_gen == gen) { }
            __threadfence();
        }
    }
    __syncthreads();
}

// ========== k_pre: weights + gt downsample (persistent) ==========
__global__ void __launch_bounds__(256, 4)
k_pre(const int* __restrict__ gm) {
    __shared__ __align__(16) char smem[10496];   // srow 8KB + nib 2KB
    int tid = threadIdx.x;
    int bid = blockIdx.x;

    // ---- phase 0: resize weights (block 0) ----
    if (bid == 0 && tid < DSZ) {
        int o = tid;
        double s2 = (o + 0.5) * 8.0 - 0.5;           // 512 -> 64
        int start = 8 * o - 4;
        if (start < 0) start = 0;
        if (start > HF - 16) start = HF - 16;
        double w[16]; double norm = 0.0;
        for (int t = 0; t < 16; t++) {
            double d = fabs(s2 - (double)(start + t)) / 8.0;
            w[t] = (d < 1.0) ? (1.0 - d) : 0.0;
            norm += w[t];
        }
        for (int t = 0; t < 16; t++) {
            w[t] /= norm;
            d_w2w[o][t] = (float)w[t];
        }
        d_w2s[o] = start;
        int js = 2 * o - 2;
        if (js < 0) js = 0;
        if (js > HM - 8) js = HM - 8;
        d_ms[o] = js;
        double row[8] = {0,0,0,0,0,0,0,0};
        for (int t = 0; t < 16; t++) {
            if (w[t] <= 0.0) continue;
            int k = start + t;
            double s1 = (k + 0.5) * 0.25 - 0.5;
            double fj = floor(s1);
            int j0 = (int)fj;
            double f = s1 - fj;
            if (j0 < 0)       { j0 = 0;      f = 0.0; }
            if (j0 >= HM - 1) { j0 = HM - 1; f = 0.0; }
            int a = j0 - js;
            if (a >= 0 && a < 8) row[a] += w[t] * (1.0 - f);
            if (f > 0.0) {
                int b2 = j0 + 1 - js;
                if (b2 >= 0 && b2 < 8) row[b2] += w[t] * f;
            }
        }
        for (int t = 0; t < 8; t++) d_mw[o][t] = (float)row[t];
    }
    grid_barrier();

    // ---- phase 1: mds1 (4 gt rows/unit, all 256 threads conv) ----
    {
        int*      srow = (int*)smem;                 // [4][512]
        unsigned* nib  = (unsigned*)(smem + 8192);   // [4][128]
        for (int u = bid; u < MDS1_UNITS; u += NBLK_PRE) {
#pragma unroll
            for (int li = 0; li < 2; li++) {
                int flat = tid + 256 * li;           // 0..511
                int rl = flat >> 7;                  // 0..3
                int x4 = flat & 127;
                const int4* rp = (const int4*)(gm + ((long)u * 4 + rl) * HF);
                int4 v = rp[x4];
                int* s = &srow[rl * 512 + x4 * 4];
                s[0] = v.x; s[1] = v.y; s[2] = v.z; s[3] = v.w;
                nib[rl * 128 + x4] = (v.x ? 1u : 0u) | (v.y ? 2u : 0u) |
                                     (v.z ? 4u : 0u) | (v.w ? 8u : 0u);
            }
            __syncthreads();
            if (tid < 64) {
                int rl = tid >> 4, w = tid & 15;
                unsigned wv = 0;
#pragma unroll
                for (int k = 0; k < 8; k++)
                    wv |= nib[rl * 128 + w * 8 + k] << (4 * k);
                d_gbits[((long)u * 4 + rl) * 16 + w] = wv;
            }
            {
                int rl = tid >> 6, ox = tid & 63;
                int st = d_w2s[ox];                  // multiple of 4
                const int4* cv = (const int4*)&srow[rl * 512 + st];
                float s = 0.f;
#pragma unroll
                for (int t4i = 0; t4i < 4; t4i++) {
                    int4 q = cv[t4i];
                    s += d_w2w[ox][t4i*4+0] * (float)q.x;
                    s += d_w2w[ox][t4i*4+1] * (float)q.y;
                    s += d_w2w[ox][t4i*4+2] * (float)q.z;
                    s += d_w2w[ox][t4i*4+3] * (float)q.w;
                }
                d_tmp1[((long)u * 4 + rl) * DSZ + ox] = s;
            }
            __syncthreads();
        }
    }
    grid_barrier();

    // ---- phase 2: mds2 (+ per-block partial sums) ----
    {
        float* sh = (float*)smem;   // [256]
        for (int u = bid; u < MDS2_UNITS; u += NBLK_PRE) {
            int idx = u * 256 + tid;
            int ox = idx & 63;
            int oy = (idx >> 6) & 63;
            int bn = idx >> 12;
            int s0 = d_w2s[oy];
            const float* col = d_tmp1 + (bn * HF + s0) * DSZ + ox;
            float s = 0.f;
#pragma unroll
            for (int t = 0; t < 16; t++) s += d_w2w[oy][t] * col[t * DSZ];
            d_mds[idx] = s;
            sh[tid] = s;
            __syncthreads();
            for (int st = 128; st > 0; st >>= 1) {
                if (tid < st) sh[tid] += sh[tid + st];
                __syncthreads();
            }
            if (tid == 0) d_msp[u] = sh[0];
            __syncthreads();
        }
    }
}

// ========== k_cost: fused query downsample (vertical-first) + cost =========
#define JSCALE32 1048576.0
__global__ void __launch_bounds__(512) k_cost(const float* __restrict__ pm,
                                              const float* __restrict__ logits,
                                              const int* __restrict__ labels) {
    __shared__ float s_vt[DSZ * CVT_STRIDE];   // [64][132] = 33.8KB
    __shared__ float s_mw[DSZ][8];
    __shared__ int   s_ms[DSZ];
    __shared__ float s_fa[NGT][16], s_ia[NGT][16];
    __shared__ float s_c0[16], s_pr[16];

    int m  = blockIdx.x;            // (l*B+b)*Q + q
    int lb = m / QQQ;
    int q  = m - lb * QQQ;
    int b  = lb % BBB;
    int tid  = threadIdx.x;
    int wid  = tid >> 5;
    int lane = tid & 31;

    if (tid < DSZ) {
        s_ms[tid] = d_ms[tid];
#pragma unroll
        for (int t = 0; t < 8; t++) s_mw[tid][t] = d_mw[tid][t];
    }
    __syncthreads();

    // ---- stage V: vertical downsample 128x128 -> 64x128 (coalesced gmem) --
    const float* pmb = pm + (long)m * (HM * HM);
#pragma unroll
    for (int k = 0; k < 16; k++) {
        int o  = tid + 512 * k;        // 0..8191
        int oy = o >> 7;               // 0..63
        int xx = o & 127;
        const float* col = pmb + s_ms[oy] * HM + xx;
        float acc = 0.f;
#pragma unroll
        for (int t = 0; t < 8; t++) acc += s_mw[oy][t] * col[t * HM];
        s_vt[oy * CVT_STRIDE + xx] = acc;
    }
    __syncthreads();

    // ---- stage H: horizontal downsample -> x[8] (px = tid*8 + k) ----
    int oy  = tid >> 3;
    int ox0 = (tid & 7) * 8;
    float x[8];
#pragma unroll
    for (int k = 0; k < 8; k++) {
        int ox = ox0 + k;
        const float* rp = &s_vt[oy * CVT_STRIDE + s_ms[ox]];
        float acc = 0.f;
#pragma unroll
        for (int t = 0; t < 8; t++) acc += s_mw[ox][t] * rp[t];
        x[k] = acc;
    }

    // ---- per-pixel coefficients ----
    float c1[8], c2[8], c3[8], prv[8];
    float c0s = 0.f, prs = 0.f;
#pragma unroll
    for (int k = 0; k < 8; k++) {
        float xx = x[k];
        float e = __expf(-fabsf(xx));
        float inv = __fdividef(1.f, 1.f + e);
        float pr = (xx >= 0.f) ? inv : e * inv;
        float sp = fmaxf(xx, 0.f) + __logf(1.f + e);
        float a  = 1.f - 2.f * pr;
        float pr2 = pr * pr;
        c0s += pr2 * sp;
        c1[k] = 2.f * pr * a * sp - pr2 * xx;
        c2[k] = a * a * sp - 2.f * pr * a * xx;
        c3[k] = -a * a * xx;
        prv[k] = pr;
        prs += pr;
    }
#pragma unroll
    for (int off = 16; off; off >>= 1) {
        c0s += __shfl_down_sync(0xffffffffu, c0s, off);
        prs += __shfl_down_sync(0xffffffffu, prs, off);
    }
    if (lane == 0) { s_c0[wid] = c0s; s_pr[wid] = prs; }

    // ---- gt loop: per-warp partials ----
    const float* tb = d_mds + (long)b * NGT * PPX;
#pragma unroll 2
    for (int n = 0; n < NGT; n++) {
        const float4* t4 = (const float4*)(tb + (long)n * PPX) + tid * 2;
        float4 ta = t4[0], tb4 = t4[1];
        float ts[8] = {ta.x, ta.y, ta.z, ta.w, tb4.x, tb4.y, tb4.z, tb4.w};
        float fa = 0.f, ia = 0.f;
#pragma unroll
        for (int k = 0; k < 8; k++) {
            float t = ts[k];
            fa += ((c3[k] * t + c2[k]) * t + c1[k]) * t;
            ia += prv[k] * t;
        }
#pragma unroll
        for (int off = 16; off; off >>= 1) {
            fa += __shfl_down_sync(0xffffffffu, fa, off);
            ia += __shfl_down_sync(0xffffffffu, ia, off);
        }
        if (lane == 0) { s_fa[n][wid] = fa; s_ia[n][wid] = ia; }
    }
    __syncthreads();

    if (tid < NGT) {
        int n = tid;
        float fs = 0.f, is2 = 0.f, c0 = 0.f, pa = 0.f;
#pragma unroll
        for (int w = 0; w < 16; w++) {
            fs += s_fa[n][w]; is2 += s_ia[n][w];
            c0 += s_c0[w];    pa  += s_pr[w];
        }
        float msum = 0.f;
        const float* mp = d_msp + (b * NGT + n) * 16;
#pragma unroll
        for (int k = 0; k < 16; k++) msum += mp[k];
        float focal = 0.25f * (c0 + fs) * (1.f / (float)PPX);
        float dice  = 1.f - (2.f * is2 + 1.f) / (pa + msum + 1.f);
        const float* lg = logits + (long)m * CCC;
        float x0 = lg[0], x1 = lg[1];
        float mx = fmaxf(x0, x1);
        float e0 = __expf(x0 - mx), e1 = __expf(x1 - mx);
        float is = __fdividef(1.f, e0 + e1);
        int lab = labels[b * NGT + n];
        float cc = -((lab ? e1 : e0) * is);
        d_costTi[(long)lb * (NGT * QQQ) + n * QQQ + q] =
            __double2int_rn((double)(cc + focal + dice) * JSCALE32);
    }
}

// ========== nop spacer ==========
__global__ void k_nop() {}

// ========== Hungarian — lapjv frozen-potential Dijkstra (int32 exact) =====
#define JINF32 0x3FFFFFFF
#define PBIAS  (1 << 23)
#define PMAX   ((1 << 24) - 1)
__global__ void k_jv() {
    int inst = blockIdx.x;
    int lane = threadIdx.x;
    __shared__ int Cs[NGT * QQQ];
    __shared__ int u[NGT + 1];
    __shared__ int p[QQQ + 1], way[QQQ + 1];
    const int* Cg = d_costTi + (long)inst * NGT * QQQ;
    for (int k = lane; k < NGT * QQQ; k += 32) Cs[k] = Cg[k];
    for (int k = lane; k <= QQQ; k += 32) { p[k] = 0; way[k] = 0; }
    for (int k = lane; k <= NGT; k += 32) u[k] = 0;
    int v[4];
#pragma unroll
    for (int s = 0; s < 4; s++) v[s] = 0;
    __syncwarp();

    for (int i = 1; i <= NGT; i++) {
        if (lane == 0) p[0] = i;
        int dist[4];
        unsigned used_b = 0;
#pragma unroll
        for (int s = 0; s < 4; s++) dist[s] = JINF32;
        int D = 0;
        int j0 = 0;
        __syncwarp();
        while (true) {
            int i0 = p[j0];
            if (i0 == 0) break;               // free column found
            if (j0 > 0) {                     // mark used
                int s = (j0 - 1) >> 5, ol = (j0 - 1) & 31;
                if (lane == ol) used_b |= (1 << s);
            }
            int base = D - u[i0];
            const int* crow = &Cs[(i0 - 1) * QQQ - 1];
            unsigned bk = 0xFFFFFFFFu;
#pragma unroll
            for (int s = 0; s < 4; s++) {
                int j = 1 + lane + 32 * s;
                if (j <= QQQ && !((used_b >> s) & 1)) {
                    int cand = crow[j] + base - v[s];
                    if (cand < dist[s]) { dist[s] = cand; way[j] = j0; }
                    int kv = dist[s] + PBIAS;
                    kv = kv < 0 ? 0 : (kv > PMAX ? PMAX : kv);
                    unsigned key = ((unsigned)kv << 7) | (unsigned)j;
                    if (key < bk) bk = key;
                }
            }
            unsigned mk = __reduce_min_sync(0xffffffffu, bk);
            j0 = (int)(mk & 127u);
            D  = (int)(mk >> 7) - PBIAS;
        }
        __syncwarp();
#pragma unroll
        for (int s = 0; s < 4; s++) {
            int j = 1 + lane + 32 * s;
            if (j <= QQQ && ((used_b >> s) & 1)) {
                v[s] += dist[s] - D;
                u[p[j]] += D - dist[s];
            }
        }
        if (lane == 0) u[i] += D;
        __syncwarp();
        if (lane == 0) {
            while (j0) { int j1 = way[j0]; p[j0] = p[j1]; j0 = j1; }
        }
        __syncwarp();
    }
    for (int j = 1 + lane; j <= QQQ; j += 32)
        if (p[j] > 0) d_qmatch[inst * NGT + (p[j] - 1)] = j - 1;
}

// ========== full-res mask loss (bit-packed gt) ==========
__global__ void __launch_bounds__(256) k_maskloss(const float* __restrict__ pm) {
    int P   = blockIdx.x >> 6;     // pair 0..119
    int blk = blockIdx.x & 63;
    int inst = P / NGT;
    int n    = P - inst * NGT;
    int b    = inst % BBB;
    int q    = d_qmatch[P];
    const float* xm = pm + ((long)(inst * QQQ + q)) * HM * HM;
    const unsigned* gb = d_gbits + (long)(b * NGT + n) * HF * 16;

    int tile = blk * 256 + threadIdx.x;   // 0..16383
    int tx = tile & 127, ty = tile >> 7;
    int xm1 = tx > 0 ? tx - 1 : 0;
    int xp1 = tx < 127 ? tx + 1 : 127;
    int ym1 = ty > 0 ? ty - 1 : 0;
    int yp1 = ty < 127 ? ty + 1 : 127;

    float h[3][4];
    int rows[3] = {ym1, ty, yp1};
#pragma unroll
    for (int r = 0; r < 3; r++) {
        const float* rp = xm + rows[r] * HM;
        float v0 = rp[xm1], v1 = rp[tx], v2 = rp[xp1];
        h[r][0] = 0.375f * v0 + 0.625f * v1;
        h[r][1] = 0.125f * v0 + 0.875f * v1;
        h[r][2] = 0.875f * v1 + 0.125f * v2;
        h[r][3] = 0.625f * v1 + 0.375f * v2;
    }
    const float wA[4] = {0.375f, 0.125f, 0.875f, 0.625f};
    const float wB[4] = {0.625f, 0.875f, 0.125f, 0.375f};

    float fac = 0.f, prs = 0.f, ins = 0.f, gts = 0.f;
#pragma unroll
    for (int phy = 0; phy < 4; phy++) {
        int ra = (phy < 2) ? 0 : 1;
        int rb = ra + 1;
        int row = 4 * ty + phy;
        unsigned wv = gb[row * 16 + (tx >> 3)];
        unsigned nb = (wv >> ((tx & 7) * 4)) & 0xFu;
        gts += (float)__popc(nb);
#pragma unroll
        for (int phx = 0; phx < 4; phx++) {
            float x = wA[phy] * h[ra][phx] + wB[phy] * h[rb][phx];
            float e = __expf(-fabsf(x));
            float inv = __fdividef(1.f, 1.f + e);
            float pr = (x >= 0.f) ? inv : e * inv;
            float sp = fmaxf(x, 0.f) + __logf(1.f + e);
            if ((nb >> phx) & 1u) {
                float om = 1.f - pr;
                fac += 0.25f * om * om * (sp - x);
                ins += pr;
            } else {
                fac += 0.75f * pr * pr * sp;
            }
            prs += pr;
        }
    }
    __shared__ float4 sh[256];
    sh[threadIdx.x] = make_float4(fac, prs, ins, gts);
    __syncthreads();
    for (int s = 128; s > 0; s >>= 1) {
        if (threadIdx.x < s) {
            float4 a = sh[threadIdx.x], c = sh[threadIdx.x + s];
            sh[threadIdx.x] = make_float4(a.x + c.x, a.y + c.y, a.z + c.z, a.w + c.w);
        }
        __syncthreads();
    }
    if (threadIdx.x == 0) d_part[P * 64 + blk] = sh[0];
}

// ========== final combine ==========
__global__ void __launch_bounds__(256) k_final(const float* __restrict__ logits,
                                               const int* __restrict__ labels,
                                               float* __restrict__ out) {
    int tid = threadIdx.x;  // 256
    __shared__ double shf[NPAIR], shd[NPAIR];
    if (tid < NPAIR) {
        double f = 0, pp = 0, ii = 0, gg = 0;
        const float4* pr = d_part + tid * 64;
#pragma unroll 8
        for (int k = 0; k < 64; k++) {
            float4 a = pr[k];
            f += (double)a.x; pp += (double)a.y;
            ii += (double)a.z; gg += (double)a.w;
        }
        shf[tid] = f;
        shd[tid] = 1.0 - (2.0 * ii + 1.0) / (pp + gg + 1.0);
    }
    __shared__ int tq[BBB * QQQ];
    __shared__ double rnum[128], rden[128];
    __shared__ double layer_ce[LLL];
    __syncthreads();
    for (int l = 0; l < LLL; l++) {
        for (int k = tid; k < BBB * QQQ; k += 256) tq[k] = CCC - 1;
        __syncthreads();
        if (tid < BBB * NGT) {
            int b = tid / NGT, n = tid - b * NGT;
            int q = d_qmatch[(l * BBB + b) * NGT + n];
            tq[b * QQQ + q] = labels[b * NGT + n];
        }
        __syncthreads();
        if (tid < 128) {
            double num = 0, den = 0;
            for (int k = tid; k < BBB * QQQ; k += 128) {
                const float* lg = logits + ((long)l * BBB * QQQ + k) * CCC;
                double x0 = lg[0], x1 = lg[1];
                double mx = fmax(x0, x1);
                double lse = mx + log(exp(x0 - mx) + exp(x1 - mx));
                int t = tq[k];
                double lp = (t ? x1 : x0) - lse;
                double w = (t == CCC - 1) ? 0.1 : 1.0;
                num += -w * lp;
                den += w;
            }
            rnum[tid] = num; rden[tid] = den;
        }
        __syncthreads();
        for (int s = 64; s > 0; s >>= 1) {
            if (tid < s) { rnum[tid] += rnum[tid + s]; rden[tid] += rden[tid + s]; }
            __syncthreads();
        }
        if (tid == 0) layer_ce[l] = rnum[0] / rden[0];
        __syncthreads();
    }
    if (tid == 0) {
        double total = 0.0;
        for (int l = 0; l < LLL; l++) {
            double fs = 0.0, ds = 0.0;
            for (int k = 0; k < BN; k++) { fs += shf[l * BN + k]; ds += shd[l * BN + k]; }
            total += 2.0 * layer_ce[l]
                   + 5.0 * fs / ((double)BN * (double)HF * (double)HF)
                   + 5.0 * ds / (double)BN;
        }
        out[0] = (float)total;
    }
}

extern "C" void kernel_launch(void* const* d_in, const int* in_sizes, int n_in,
                              void* d_out, int out_size) {
    (void)in_sizes; (void)n_in; (void)out_size;
    const float* logits = (const float*)d_in[0];   // (L,B,Q,C)
    const float* pm     = (const float*)d_in[1];   // (L,B,Q,128,128)
    const int*   labels = (const int*)d_in[2];     // (B,N)
    const int*   gm     = (const int*)d_in[3];     // (B,N,512,512)
    float* out = (float*)d_out;

    k_nop<<<1, 32>>>();                          // spacers: k_pre -> 4th
    k_nop<<<1, 32>>>();
    k_nop<<<1, 32>>>();
    k_pre<<<NBLK_PRE, 256>>>(gm);                // <- profiled
    k_cost<<<MQ, 512>>>(pm, logits, labels);
    k_jv<<<LB, 32>>>();
    k_maskloss<<<NPAIR * 64, 256>>>(pm);
    k_final<<<1, 256>>>(logits, labels, out);
}

// round 13
// speedup vs baseline: 1.1914x; 1.1914x over previous
#include <cuda_runtime.h>
#include <math.h>

// Shapes fixed by setup_inputs
#define LLL 3
#define BBB 2
#define QQQ 100
#define CCC 2
#define NGT 20
#define HM  128
#define HF  512
#define DSZ 64
#define PPX (DSZ*DSZ)        // 4096
#define LB  (LLL*BBB)        // 6
#define BN  (BBB*NGT)        // 40
#define MQ  (LLL*BBB*QQQ)    // 600
#define NPAIR (LLL*BBB*NGT)  // 120

#define NBLK_PRE 592         // 4 blocks/SM on 148 SMs
#define MDS1_UNITS (BN*HF/8) // 2560 (8 rows/unit)
#define MDS2_UNITS (BN*16)   // 640

// k_cost dynamic smem: s_pm[128][132] + s_tmp[128][68]
#define CPM_STRIDE 132
#define CTMP_STRIDE 68
#define CSMEM ((128*CPM_STRIDE + 128*CTMP_STRIDE) * 4)   // 102400 B

// ---------------- static device scratch (no allocation) ----------------
__device__ float  d_w2w[DSZ][16];
__device__ int    d_w2s[DSZ];
__device__ float  d_mw[DSZ][8];
__device__ int    d_ms[DSZ];
__device__ float  d_tmp1[BN*HF*DSZ];
__device__ float  d_mds[BN*PPX];
__device__ float  d_msp[BN*16];
__device__ unsigned d_gbits[BN*HF*16];
__device__ int    d_costTi[LB*NGT*QQQ];   // quantized cost (scale 2^20)
__device__ int    d_qmatch[LB*NGT];
__device__ float4 d_part[NPAIR*64];       // mask-loss partials

// ---- grid barrier state (count self-resets via atomicInc wrap) ----
__device__ unsigned g_count = 0;
__device__ volatile unsigned g_gen = 0;

__device__ __forceinline__ void grid_barrier() {
    __syncthreads();
    if (threadIdx.x == 0) {
        unsigned gen = g_gen;
        __threadfence();
        unsigned t = atomicInc(&g_count, NBLK_PRE - 1);
        if (t == NBLK_PRE - 1) {
            __threadfence();
            g_gen = gen + 1;
        } else {
            while (g_gen == gen) { }
            __threadfence();
        }
    }
    __syncthreads();
}

// ========== k_pre: weights + gt downsample (8 rows/unit, MLP=4) ==========
__global__ void __launch_bounds__(256, 4)
k_pre(const int* __restrict__ gm) {
    __shared__ __align__(16) char smem[20992];   // srow 16KB + nib 4KB
    int tid = threadIdx.x;
    int bid = blockIdx.x;

    // ---- phase 0: resize weights (block 0) ----
    if (bid == 0 && tid < DSZ) {
        int o = tid;
        double s2 = (o + 0.5) * 8.0 - 0.5;           // 512 -> 64
        int start = 8 * o - 4;
        if (start < 0) start = 0;
        if (start > HF - 16) start = HF - 16;
        double w[16]; double norm = 0.0;
        for (int t = 0; t < 16; t++) {
            double d = fabs(s2 - (double)(start + t)) / 8.0;
            w[t] = (d < 1.0) ? (1.0 - d) : 0.0;
            norm += w[t];
        }
        for (int t = 0; t < 16; t++) {
            w[t] /= norm;
            d_w2w[o][t] = (float)w[t];
        }
        d_w2s[o] = start;
        int js = 2 * o - 2;
        if (js < 0) js = 0;
        if (js > HM - 8) js = HM - 8;
        d_ms[o] = js;
        double row[8] = {0,0,0,0,0,0,0,0};
        for (int t = 0; t < 16; t++) {
            if (w[t] <= 0.0) continue;
            int k = start + t;
            double s1 = (k + 0.5) * 0.25 - 0.5;
            double fj = floor(s1);
            int j0 = (int)fj;
            double f = s1 - fj;
            if (j0 < 0)       { j0 = 0;      f = 0.0; }
            if (j0 >= HM - 1) { j0 = HM - 1; f = 0.0; }
            int a = j0 - js;
            if (a >= 0 && a < 8) row[a] += w[t] * (1.0 - f);
            if (f > 0.0) {
                int b2 = j0 + 1 - js;
                if (b2 >= 0 && b2 < 8) row[b2] += w[t] * f;
            }
        }
        for (int t = 0; t < 8; t++) d_mw[o][t] = (float)row[t];
    }
    grid_barrier();

    // ---- phase 1: mds1 (8 gt rows/unit; 4 independent LDGs per thread) ----
    {
        int*      srow = (int*)smem;                  // [8][512]
        unsigned* nib  = (unsigned*)(smem + 16384);   // [8][128]
        for (int u = bid; u < MDS1_UNITS; u += NBLK_PRE) {
            int4 vv[4];
#pragma unroll
            for (int li = 0; li < 4; li++) {
                int flat = tid + 256 * li;           // 0..1023
                int rl = flat >> 7;                  // 0..7
                int x4 = flat & 127;
                vv[li] = ((const int4*)(gm + ((long)u * 8 + rl) * HF))[x4];
            }
#pragma unroll
            for (int li = 0; li < 4; li++) {
                int flat = tid + 256 * li;
                int rl = flat >> 7;
                int x4 = flat & 127;
                int4 v = vv[li];
                int* s = &srow[rl * 512 + x4 * 4];
                s[0] = v.x; s[1] = v.y; s[2] = v.z; s[3] = v.w;
                nib[rl * 128 + x4] = (v.x ? 1u : 0u) | (v.y ? 2u : 0u) |
                                     (v.z ? 4u : 0u) | (v.w ? 8u : 0u);
            }
            __syncthreads();
            if (tid < 128) {
                int rl = tid >> 4, w = tid & 15;
                unsigned wv = 0;
#pragma unroll
                for (int k = 0; k < 8; k++)
                    wv |= nib[rl * 128 + w * 8 + k] << (4 * k);
                d_gbits[((long)u * 8 + rl) * 16 + w] = wv;
            }
#pragma unroll
            for (int li2 = 0; li2 < 2; li2++) {
                int o  = tid + 256 * li2;            // 0..511
                int rl = o >> 6, ox = o & 63;
                int st = d_w2s[ox];                  // multiple of 4
                const int4* cv = (const int4*)&srow[rl * 512 + st];
                float s = 0.f;
#pragma unroll
                for (int t4i = 0; t4i < 4; t4i++) {
                    int4 q = cv[t4i];
                    s += d_w2w[ox][t4i*4+0] * (float)q.x;
                    s += d_w2w[ox][t4i*4+1] * (float)q.y;
                    s += d_w2w[ox][t4i*4+2] * (float)q.z;
                    s += d_w2w[ox][t4i*4+3] * (float)q.w;
                }
                d_tmp1[((long)u * 8 + rl) * DSZ + ox] = s;
            }
            __syncthreads();
        }
    }
    grid_barrier();

    // ---- phase 2: mds2 (+ per-block partial sums) ----
    {
        float* sh = (float*)smem;   // [256]
        for (int u = bid; u < MDS2_UNITS; u += NBLK_PRE) {
            int idx = u * 256 + tid;
            int ox = idx & 63;
            int oy = (idx >> 6) & 63;
            int bn = idx >> 12;
            int s0 = d_w2s[oy];
            const float* col = d_tmp1 + (bn * HF + s0) * DSZ + ox;
            float s = 0.f;
#pragma unroll
            for (int t = 0; t < 16; t++) s += d_w2w[oy][t] * col[t * DSZ];
            d_mds[idx] = s;
            sh[tid] = s;
            __syncthreads();
            for (int st = 128; st > 0; st >>= 1) {
                if (tid < st) sh[tid] += sh[tid + st];
                __syncthreads();
            }
            if (tid == 0) d_msp[u] = sh[0];
            __syncthreads();
        }
    }
}

// ========== k_cost: fused qds + cost (R11 staged version, measured 63.6) ==
#define JSCALE32 1048576.0
__global__ void __launch_bounds__(512) k_cost(const float* __restrict__ pm,
                                              const float* __restrict__ logits,
                                              const int* __restrict__ labels) {
    extern __shared__ float dsm[];
    float* s_pm  = dsm;                       // [128][132]
    float* s_tmp = dsm + 128 * CPM_STRIDE;    // [128][68]
    __shared__ float s_mw[DSZ][8];
    __shared__ int   s_ms[DSZ];
    __shared__ float s_fa[NGT][16], s_ia[NGT][16];
    __shared__ float s_c0[16], s_pr[16];

    int m  = blockIdx.x;            // (l*B+b)*Q + q
    int lb = m / QQQ;
    int q  = m - lb * QQQ;
    int b  = lb % BBB;
    int tid  = threadIdx.x;
    int wid  = tid >> 5;
    int lane = tid & 31;

    if (tid < DSZ) {
        s_ms[tid] = d_ms[tid];
#pragma unroll
        for (int t = 0; t < 8; t++) s_mw[tid][t] = d_mw[tid][t];
    }

    // ---- stage A0: load full pm tile (one sync) ----
    const float4* pmv = (const float4*)(pm + (long)m * (HM * HM));
#pragma unroll
    for (int c = 0; c < 8; c++) {
        int f = tid + 512 * c;          // float4 index 0..4095
        float4 v = pmv[f];
        int row = f >> 5;
        int col = (f & 31) * 4;
        *(float4*)&s_pm[row * CPM_STRIDE + col] = v;
    }
    __syncthreads();

    // ---- stage A1: horizontal downsample -> s_tmp (one sync) ----
#pragma unroll
    for (int k = 0; k < 16; k++) {
        int o  = tid + 512 * k;         // 0..8191
        int yl = o >> 6;
        int ox = o & 63;
        const float* rp = &s_pm[yl * CPM_STRIDE + s_ms[ox]];
        float acc = 0.f;
#pragma unroll
        for (int t = 0; t < 8; t++) acc += s_mw[ox][t] * rp[t];
        s_tmp[yl * CTMP_STRIDE + ox] = acc;
    }
    __syncthreads();

    // ---- stage B: vertical downsample -> x[8] (px = tid*8 + k) ----
    int oy  = tid >> 3;
    int ox0 = (tid & 7) * 8;
    int r0  = s_ms[oy];
    float x[8];
#pragma unroll
    for (int k = 0; k < 8; k++) x[k] = 0.f;
#pragma unroll
    for (int t = 0; t < 8; t++) {
        float wv = s_mw[oy][t];
        const float* rp = &s_tmp[(r0 + t) * CTMP_STRIDE + ox0];
#pragma unroll
        for (int k = 0; k < 8; k++) x[k] += wv * rp[k];
    }

    // ---- per-pixel coefficients ----
    float c1[8], c2[8], c3[8], prv[8];
    float c0s = 0.f, prs = 0.f;
#pragma unroll
    for (int k = 0; k < 8; k++) {
        float xx = x[k];
        float e = __expf(-fabsf(xx));
        float inv = __fdividef(1.f, 1.f + e);
        float pr = (xx >= 0.f) ? inv : e * inv;
        float sp = fmaxf(xx, 0.f) + __logf(1.f + e);
        float a  = 1.f - 2.f * pr;
        float pr2 = pr * pr;
        c0s += pr2 * sp;
        c1[k] = 2.f * pr * a * sp - pr2 * xx;
        c2[k] = a * a * sp - 2.f * pr * a * xx;
        c3[k] = -a * a * xx;
        prv[k] = pr;
        prs += pr;
    }
#pragma unroll
    for (int off = 16; off; off >>= 1) {
        c0s += __shfl_down_sync(0xffffffffu, c0s, off);
        prs += __shfl_down_sync(0xffffffffu, prs, off);
    }
    if (lane == 0) { s_c0[wid] = c0s; s_pr[wid] = prs; }

    // ---- gt loop: per-warp partials ----
    const float* tb = d_mds + (long)b * NGT * PPX;
#pragma unroll 2
    for (int n = 0; n < NGT; n++) {
        const float4* t4 = (const float4*)(tb + (long)n * PPX) + tid * 2;
        float4 ta = t4[0], tb4 = t4[1];
        float ts[8] = {ta.x, ta.y, ta.z, ta.w, tb4.x, tb4.y, tb4.z, tb4.w};
        float fa = 0.f, ia = 0.f;
#pragma unroll
        for (int k = 0; k < 8; k++) {
            float t = ts[k];
            fa += ((c3[k] * t + c2[k]) * t + c1[k]) * t;
            ia += prv[k] * t;
        }
#pragma unroll
        for (int off = 16; off; off >>= 1) {
            fa += __shfl_down_sync(0xffffffffu, fa, off);
            ia += __shfl_down_sync(0xffffffffu, ia, off);
        }
        if (lane == 0) { s_fa[n][wid] = fa; s_ia[n][wid] = ia; }
    }
    __syncthreads();

    if (tid < NGT) {
        int n = tid;
        float fs = 0.f, is2 = 0.f, c0 = 0.f, pa = 0.f;
#pragma unroll
        for (int w = 0; w < 16; w++) {
            fs += s_fa[n][w]; is2 += s_ia[n][w];
            c0 += s_c0[w];    pa  += s_pr[w];
        }
        float msum = 0.f;
        const float* mp = d_msp + (b * NGT + n) * 16;
#pragma unroll
        for (int k = 0; k < 16; k++) msum += mp[k];
        float focal = 0.25f * (c0 + fs) * (1.f / (float)PPX);
        float dice  = 1.f - (2.f * is2 + 1.f) / (pa + msum + 1.f);
        const float* lg = logits + (long)m * CCC;
        float x0 = lg[0], x1 = lg[1];
        float mx = fmaxf(x0, x1);
        float e0 = __expf(x0 - mx), e1 = __expf(x1 - mx);
        float is = __fdividef(1.f, e0 + e1);
        int lab = labels[b * NGT + n];
        float cc = -((lab ? e1 : e0) * is);
        d_costTi[(long)lb * (NGT * QQQ) + n * QQQ + q] =
            __double2int_rn((double)(cc + focal + dice) * JSCALE32);
    }
}

// ========== nop spacer ==========
__global__ void k_nop() {}

// ========== Hungarian — lapjv frozen-potential Dijkstra (int32 exact) =====
#define JINF32 0x3FFFFFFF
#define PBIAS  (1 << 23)
#define PMAX   ((1 << 24) - 1)
__global__ void k_jv() {
    int inst = blockIdx.x;
    int lane = threadIdx.x;
    __shared__ int Cs[NGT * QQQ];
    __shared__ int u[NGT + 1];
    __shared__ int p[QQQ + 1], way[QQQ + 1];
    const int* Cg = d_costTi + (long)inst * NGT * QQQ;
    for (int k = lane; k < NGT * QQQ; k += 32) Cs[k] = Cg[k];
    for (int k = lane; k <= QQQ; k += 32) { p[k] = 0; way[k] = 0; }
    for (int k = lane; k <= NGT; k += 32) u[k] = 0;
    int v[4];
#pragma unroll
    for (int s = 0; s < 4; s++) v[s] = 0;
    __syncwarp();

    for (int i = 1; i <= NGT; i++) {
        if (lane == 0) p[0] = i;
        int dist[4];
        unsigned used_b = 0;
#pragma unroll
        for (int s = 0; s < 4; s++) dist[s] = JINF32;
        int D = 0;
        int j0 = 0;
        __syncwarp();
        while (true) {
            int i0 = p[j0];
            if (i0 == 0) break;               // free column found
            if (j0 > 0) {                     // mark used
                int s = (j0 - 1) >> 5, ol = (j0 - 1) & 31;
                if (lane == ol) used_b |= (1 << s);
            }
            int base = D - u[i0];
            const int* crow = &Cs[(i0 - 1) * QQQ - 1];
            unsigned bk = 0xFFFFFFFFu;
#pragma unroll
            for (int s = 0; s < 4; s++) {
                int j = 1 + lane + 32 * s;
                if (j <= QQQ && !((used_b >> s) & 1)) {
                    int cand = crow[j] + base - v[s];
                    if (cand < dist[s]) { dist[s] = cand; way[j] = j0; }
                    int kv = dist[s] + PBIAS;
                    kv = kv < 0 ? 0 : (kv > PMAX ? PMAX : kv);
                    unsigned key = ((unsigned)kv << 7) | (unsigned)j;
                    if (key < bk) bk = key;
                }
            }
            unsigned mk = __reduce_min_sync(0xffffffffu, bk);
            j0 = (int)(mk & 127u);
            D  = (int)(mk >> 7) - PBIAS;
        }
        __syncwarp();
#pragma unroll
        for (int s = 0; s < 4; s++) {
            int j = 1 + lane + 32 * s;
            if (j <= QQQ && ((used_b >> s) & 1)) {
                v[s] += dist[s] - D;
                u[p[j]] += D - dist[s];
            }
        }
        if (lane == 0) u[i] += D;
        __syncwarp();
        if (lane == 0) {
            while (j0) { int j1 = way[j0]; p[j0] = p[j1]; j0 = j1; }
        }
        __syncwarp();
    }
    for (int j = 1 + lane; j <= QQQ; j += 32)
        if (p[j] > 0) d_qmatch[inst * NGT + (p[j] - 1)] = j - 1;
}

// ========== full-res mask loss (bit-packed gt) ==========
__global__ void __launch_bounds__(256) k_maskloss(const float* __restrict__ pm) {
    int P   = blockIdx.x >> 6;     // pair 0..119
    int blk = blockIdx.x & 63;
    int inst = P / NGT;
    int n    = P - inst * NGT;
    int b    = inst % BBB;
    int q    = d_qmatch[P];
    const float* xm = pm + ((long)(inst * QQQ + q)) * HM * HM;
    const unsigned* gb = d_gbits + (long)(b * NGT + n) * HF * 16;

    int tile = blk * 256 + threadIdx.x;   // 0..16383
    int tx = tile & 127, ty = tile >> 7;
    int xm1 = tx > 0 ? tx - 1 : 0;
    int xp1 = tx < 127 ? tx + 1 : 127;
    int ym1 = ty > 0 ? ty - 1 : 0;
    int yp1 = ty < 127 ? ty + 1 : 127;

    float h[3][4];
    int rows[3] = {ym1, ty, yp1};
#pragma unroll
    for (int r = 0; r < 3; r++) {
        const float* rp = xm + rows[r] * HM;
        float v0 = rp[xm1], v1 = rp[tx], v2 = rp[xp1];
        h[r][0] = 0.375f * v0 + 0.625f * v1;
        h[r][1] = 0.125f * v0 + 0.875f * v1;
        h[r][2] = 0.875f * v1 + 0.125f * v2;
        h[r][3] = 0.625f * v1 + 0.375f * v2;
    }
    const float wA[4] = {0.375f, 0.125f, 0.875f, 0.625f};
    const float wB[4] = {0.625f, 0.875f, 0.125f, 0.375f};

    float fac = 0.f, prs = 0.f, ins = 0.f, gts = 0.f;
#pragma unroll
    for (int phy = 0; phy < 4; phy++) {
        int ra = (phy < 2) ? 0 : 1;
        int rb = ra + 1;
        int row = 4 * ty + phy;
        unsigned wv = gb[row * 16 + (tx >> 3)];
        unsigned nb = (wv >> ((tx & 7) * 4)) & 0xFu;
        gts += (float)__popc(nb);
#pragma unroll
        for (int phx = 0; phx < 4; phx++) {
            float x = wA[phy] * h[ra][phx] + wB[phy] * h[rb][phx];
            float e = __expf(-fabsf(x));
            float inv = __fdividef(1.f, 1.f + e);
            float pr = (x >= 0.f) ? inv : e * inv;
            float sp = fmaxf(x, 0.f) + __logf(1.f + e);
            if ((nb >> phx) & 1u) {
                float om = 1.f - pr;
                fac += 0.25f * om * om * (sp - x);
                ins += pr;
            } else {
                fac += 0.75f * pr * pr * sp;
            }
            prs += pr;
        }
    }
    __shared__ float4 sh[256];
    sh[threadIdx.x] = make_float4(fac, prs, ins, gts);
    __syncthreads();
    for (int s = 128; s > 0; s >>= 1) {
        if (threadIdx.x < s) {
            float4 a = sh[threadIdx.x], c = sh[threadIdx.x + s];
            sh[threadIdx.x] = make_float4(a.x + c.x, a.y + c.y, a.z + c.z, a.w + c.w);
        }
        __syncthreads();
    }
    if (threadIdx.x == 0) d_part[P * 64 + blk] = sh[0];
}

// ========== final combine ==========
__global__ void __launch_bounds__(256) k_final(const float* __restrict__ logits,
                                               const int* __restrict__ labels,
                                               float* __restrict__ out) {
    int tid = threadIdx.x;  // 256
    __shared__ double shf[NPAIR], shd[NPAIR];
    if (tid < NPAIR) {
        double f = 0, pp = 0, ii = 0, gg = 0;
        const float4* pr = d_part + tid * 64;
#pragma unroll 8
        for (int k = 0; k < 64; k++) {
            float4 a = pr[k];
            f += (double)a.x; pp += (double)a.y;
            ii += (double)a.z; gg += (double)a.w;
        }
        shf[tid] = f;
        shd[tid] = 1.0 - (2.0 * ii + 1.0) / (pp + gg + 1.0);
    }
    __shared__ int tq[BBB * QQQ];
    __shared__ double rnum[128], rden[128];
    __shared__ double layer_ce[LLL];
    __syncthreads();
    for (int l = 0; l < LLL; l++) {
        for (int k = tid; k < BBB * QQQ; k += 256) tq[k] = CCC - 1;
        __syncthreads();
        if (tid < BBB * NGT) {
            int b = tid / NGT, n = tid - b * NGT;
            int q = d_qmatch[(l * BBB + b) * NGT + n];
            tq[b * QQQ + q] = labels[b * NGT + n];
        }
        __syncthreads();
        if (tid < 128) {
            double num = 0, den = 0;
            for (int k = tid; k < BBB * QQQ; k += 128) {
                const float* lg = logits + ((long)l * BBB * QQQ + k) * CCC;
                double x0 = lg[0], x1 = lg[1];
                double mx = fmax(x0, x1);
                double lse = mx + log(exp(x0 - mx) + exp(x1 - mx));
                int t = tq[k];
                double lp = (t ? x1 : x0) - lse;
                double w = (t == CCC - 1) ? 0.1 : 1.0;
                num += -w * lp;
                den += w;
            }
            rnum[tid] = num; rden[tid] = den;
        }
        __syncthreads();
        for (int s = 64; s > 0; s >>= 1) {
            if (tid < s) { rnum[tid] += rnum[tid + s]; rden[tid] += rden[tid + s]; }
            __syncthreads();
        }
        if (tid == 0) layer_ce[l] = rnum[0] / rden[0];
        __syncthreads();
    }
    if (tid == 0) {
        double total = 0.0;
        for (int l = 0; l < LLL; l++) {
            double fs = 0.0, ds = 0.0;
            for (int k = 0; k < BN; k++) { fs += shf[l * BN + k]; ds += shd[l * BN + k]; }
            total += 2.0 * layer_ce[l]
                   + 5.0 * fs / ((double)BN * (double)HF * (double)HF)
                   + 5.0 * ds / (double)BN;
        }
        out[0] = (float)total;
    }
}

extern "C" void kernel_launch(void* const* d_in, const int* in_sizes, int n_in,
                              void* d_out, int out_size) {
    (void)in_sizes; (void)n_in; (void)out_size;
    const float* logits = (const float*)d_in[0];   // (L,B,Q,C)
    const float* pm     = (const float*)d_in[1];   // (L,B,Q,128,128)
    const int*   labels = (const int*)d_in[2];     // (B,N)
    const int*   gm     = (const int*)d_in[3];     // (B,N,512,512)
    float* out = (float*)d_out;

    cudaFuncSetAttribute(k_cost, cudaFuncAttributeMaxDynamicSharedMemorySize,
                         CSMEM);

    k_nop<<<1, 32>>>();                              // 1 (spacer)
    k_pre<<<NBLK_PRE, 256>>>(gm);                    // 2
    k_cost<<<MQ, 512, CSMEM>>>(pm, logits, labels);  // 3
    k_jv<<<LB, 32>>>();                              // 4  <- profiled
    k_maskloss<<<NPAIR * 64, 256>>>(pm);             // 5
    k_final<<<1, 256>>>(logits, labels, out);        // 6
}